// round 16
// baseline (speedup 1.0000x reference)
#include <cuda_runtime.h>
#include <math.h>

// DehLoss: O(n^2) pairwise Gaussian-kernel loss, n = 8192.
// R_i = g1_i + log(y_i), h = 1.3*n^-0.2, dr_ij = (R_i - R_j)/h
// Dk_j = sum_i d_i*phi(dr_ij);  LP_j = sum_i L_i*ndtr(dr_ij), L_i = exp(g2_i-g1_i)
// out = -(S1+S2+S3+S4)
//
// R16 (vs R15): prep stripped to ordering only. S12 moved into reduce
// (per-thread acc contribution); Lsum computed block-redundantly in reduce
// from g_sval in fixed index order (deterministic). Prep phase A is now just
// load -> log/exp -> histogram -> store -> spin. Pair kernel byte-identical
// (SPLITS=64). 3 launches.

#define N      8192
#define SPLITS 64
#define CHUNK  (N / SPLITS)   // 128 columns per split
#define JT     128
#define GX     (N / JT)       // 64 j-blocks
#define RB     32             // reduce blocks
#define PB     32             // prep blocks
#define PT     256
#define NB     64             // buckets
#define NW     (PT / 32)      // warps per prep block
#define BAND   6.0f
#define BLO    (-32.0f)       // fixed bucket range (Rh provably in +-24)

typedef unsigned long long u64;

__device__ float  g_skey[N];      // bucket-ordered Rh
__device__ float  g_sval[N];      // bucket-ordered +-L (sign = delta flag)
__device__ float  g_rowRh[N];     // bucket-ordered Rh of flagged rows
__device__ int    g_M;            // number of flagged rows
__device__ int    g_c1;           // prep spin counter (reset by reduce)
__device__ int    g_ctr;          // reduce last-block counter
__device__ int    g_hist[NB * PB], g_histF[NB * PB];   // [bucket*PB + block]
__device__ float  g_partDk[N * SPLITS];   // [c*SPLITS + s]
__device__ float  g_partLP[N * SPLITS];
__device__ double g_bsum[RB];

__device__ __forceinline__ float ex2f_(float x) {
    float r; asm("ex2.approx.ftz.f32 %0, %1;" : "=f"(r) : "f"(x)); return r;
}
__device__ __forceinline__ float rcpf_(float x) {
    float r; asm("rcp.approx.ftz.f32 %0, %1;" : "=f"(r) : "f"(x)); return r;
}
__device__ __forceinline__ u64 pk2(float lo, float hi) {
    u64 r; asm("mov.b64 %0, {%1, %2};" : "=l"(r) : "f"(lo), "f"(hi)); return r;
}
__device__ __forceinline__ void upk2(u64 v, float& lo, float& hi) {
    asm("mov.b64 {%0, %1}, %2;" : "=f"(lo), "=f"(hi) : "l"(v));
}
__device__ __forceinline__ u64 fma2_(u64 a, u64 b, u64 c) {
    u64 d; asm("fma.rn.f32x2 %0, %1, %2, %3;" : "=l"(d) : "l"(a), "l"(b), "l"(c)); return d;
}
__device__ __forceinline__ u64 mul2_(u64 a, u64 b) {
    u64 d; asm("mul.rn.f32x2 %0, %1, %2;" : "=l"(d) : "l"(a), "l"(b)); return d;
}
__device__ __forceinline__ u64 add2_(u64 a, u64 b) {
    u64 d; asm("add.rn.f32x2 %0, %1, %2;" : "=l"(d) : "l"(a), "l"(b)); return d;
}

// Resident-grid spin barrier: all PB blocks co-resident (32 << 148 SMs).
__device__ __forceinline__ void grid_spin(int* ctr, int tid) {
    __threadfence();
    __syncthreads();
    if (tid == 0) {
        atomicAdd(ctr, 1);
        volatile int* p = ctr;
        while (*p < PB) { }
    }
    __syncthreads();
    __threadfence();
}

__global__ void __launch_bounds__(PT) prep_kernel(const float* __restrict__ mz,
                                                  const float* __restrict__ y,
                                                  const float* __restrict__ delta,
                                                  float inv_h) {
    __shared__ int    sH[NB], sHF[NB];
    __shared__ int    sPb[NB], sPbF[NB];
    __shared__ int    sWs[2], sWsF[2];
    __shared__ int    H[NB * PB];     // 8 KB, [bucket*PB + block]
    __shared__ int    HF[NB * PB];    // 8 KB
    __shared__ int    W[NW * NB], WF[NW * NB];
    const int b = blockIdx.x, t = threadIdx.x;
    const int lane = t & 31, w = t >> 5;
    const int j = b * PT + t;

    // ---- phase A (minimal): values + histogram + store ----
    float2 g = ((const float2*)mz)[j];
    float R    = g.x + logf(y[j]);
    float Rh   = R * inv_h;
    float L    = expf(g.y - g.x);
    int   flag = delta[j] > 0.5f;
    float val  = flag ? -L : L;
    const int bk = min(max((int)(Rh - BLO), 0), NB - 1);   // fixed bounds, scale 1

    if (t < NB) { sH[t] = 0; sHF[t] = 0; }
    __syncthreads();
    atomicAdd(&sH[bk], 1);
    if (flag) atomicAdd(&sHF[bk], 1);
    __syncthreads();
    if (t < NB) { g_hist[t * PB + b] = sH[t]; g_histF[t * PB + b] = sHF[t]; }

    grid_spin(&g_c1, t);

    // ---- phase B: global ranks + scatter ----
    for (int k = t; k < NB * PB; k += PT) { H[k] = g_hist[k]; HF[k] = g_histF[k]; }
    for (int k = t; k < NW * NB; k += PT) { W[k] = 0; WF[k] = 0; }
    __syncthreads();

    // bucket totals + 2-warp inclusive shfl scan (threads 0..63)
    int tot = 0, totF = 0, incl = 0, inclF = 0;
    if (t < NB) {
        #pragma unroll
        for (int q = 0; q < PB; ++q) { tot += H[t * PB + q]; totF += HF[t * PB + q]; }
        incl = tot; inclF = totF;
        #pragma unroll
        for (int off = 1; off < 32; off <<= 1) {
            int n  = __shfl_up_sync(0xFFFFFFFFu, incl,  off);
            int nF = __shfl_up_sync(0xFFFFFFFFu, inclF, off);
            if (lane >= off) { incl += n; inclF += nF; }
        }
        if (lane == 31) { sWs[w] = incl; sWsF[w] = inclF; }
    }
    // stable in-warp rank (all 256 threads; independent of scan)
    unsigned mask = __match_any_sync(0xFFFFFFFFu, bk);
    unsigned ltm  = (1u << lane) - 1u;
    int rw = __popc(mask & ltm);
    unsigned flgbal = __ballot_sync(0xFFFFFFFFu, flag);
    unsigned maskF  = mask & flgbal;
    int rwF = __popc(maskF & ltm);
    if ((mask & ltm) == 0) W[w * NB + bk] = __popc(mask);
    if (flag && ((maskF & ltm) == 0)) WF[w * NB + bk] = __popc(maskF);
    __syncthreads();

    if (t < NB) {
        int add  = (t >= 32) ? sWs[0]  : 0;
        int addF = (t >= 32) ? sWsF[0] : 0;
        sPb[t]  = incl  + add  - tot;    // exclusive bucket prefix
        sPbF[t] = inclF + addF - totF;
        if (b == 0 && t == NB - 1) g_M = inclF + addF;   // total flagged
    }
    __syncthreads();

    int below = 0, belowF = 0;
    for (int q = 0; q < b; ++q) { below += H[bk * PB + q]; belowF += HF[bk * PB + q]; }
    int woff = 0, woffF = 0;
    #pragma unroll
    for (int q = 0; q < NW; ++q) {
        if (q < w) { woff += W[q * NB + bk]; woffF += WF[q * NB + bk]; }
    }
    int dest = sPb[bk] + below + woff + rw;
    g_skey[dest] = Rh;
    g_sval[dest] = val;
    if (flag) g_rowRh[sPbF[bk] + belowF + woffF + rwF] = Rh;
}

__global__ void __launch_bounds__(JT) pair_kernel() {
    __shared__ float4 shA[CHUNK / 2];
    __shared__ float2 shL[CHUNK / 2];
    __shared__ float  wred[5][JT / 32];
    const int M = g_M;
    const int c0 = blockIdx.x * JT;
    if (c0 >= M) return;

    const int c  = c0 + threadIdx.x;
    const int cc = min(c, M - 1);
    const int s  = blockIdx.y;
    const float Rhj = g_rowRh[cc];

    // fill smem tile + per-thread chunk stats
    float cmin = 1e30f, cmax = -1e30f, cls = 0.0f;
    const int cbase = s * CHUNK;
    for (int k = threadIdx.x; k < CHUNK / 2; k += JT) {
        float kx = g_skey[cbase + 2 * k], ky = g_skey[cbase + 2 * k + 1];
        float vx = g_sval[cbase + 2 * k], vy = g_sval[cbase + 2 * k + 1];
        float ax = fabsf(vx), ay = fabsf(vy);
        shA[k] = make_float4(kx, ky, vx < 0.0f ? 1.0f : 0.0f, vy < 0.0f ? 1.0f : 0.0f);
        shL[k] = make_float2(ax, ay);
        cmin = fminf(cmin, fminf(kx, ky));
        cmax = fmaxf(cmax, fmaxf(kx, ky));
        cls += ax + ay;
    }
    float rmin = Rhj, rmax = Rhj;
    #pragma unroll
    for (int o = 16; o > 0; o >>= 1) {
        cmin = fminf(cmin, __shfl_down_sync(0xFFFFFFFFu, cmin, o));
        cmax = fmaxf(cmax, __shfl_down_sync(0xFFFFFFFFu, cmax, o));
        cls += __shfl_down_sync(0xFFFFFFFFu, cls, o);
        rmin = fminf(rmin, __shfl_down_sync(0xFFFFFFFFu, rmin, o));
        rmax = fmaxf(rmax, __shfl_down_sync(0xFFFFFFFFu, rmax, o));
    }
    {
        int w = threadIdx.x >> 5, lane = threadIdx.x & 31;
        if (lane == 0) {
            wred[0][w] = cmin; wred[1][w] = cmax; wred[2][w] = cls;
            wred[3][w] = rmin; wred[4][w] = rmax;
        }
    }
    __syncthreads();   // also orders the smem tile for the loop below
    cmin = wred[0][0]; cmax = wred[1][0]; cls = wred[2][0];
    rmin = wred[3][0]; rmax = wred[4][0];
    #pragma unroll
    for (int q = 1; q < JT / 32; ++q) {
        cmin = fminf(cmin, wred[0][q]); cmax = fmaxf(cmax, wred[1][q]); cls += wred[2][q];
        rmin = fminf(rmin, wred[3][q]); rmax = fmaxf(rmax, wred[4][q]);
    }

    // band skip: tile fully outside |dr| <= BAND -> analytic contribution
    if (cmin > rmax + BAND) {     // all dr >> 0: ndtr=1, phi=0
        if (c < M) { g_partDk[c * SPLITS + s] = 0.0f; g_partLP[c * SPLITS + s] =  0.5f * cls; }
        return;
    }
    if (cmax < rmin - BAND) {     // all dr << 0: ndtr=0, phi=0
        if (c < M) { g_partDk[c * SPLITS + s] = 0.0f; g_partLP[c * SPLITS + s] = -0.5f * cls; }
        return;
    }

    // C1 = -0.5*log2(e), C2 = log2(1/sqrt(2*pi)); AS 26.2.16 coeffs negated.
    const u64 nRhj2 = pk2(-Rhj, -Rhj);
    const u64 C1_2  = pk2(-0.72134752044448170f, -0.72134752044448170f);
    const u64 C2_2  = pk2(-1.32574806473615923f, -1.32574806473615923f);
    const u64 PP2   = pk2(0.33267f, 0.33267f);
    const u64 ONE2  = pk2(1.0f, 1.0f);
    const u64 HALF2 = pk2(0.5f, 0.5f);
    const u64 NA1_2 = pk2(-0.4361836f, -0.4361836f);
    const u64 NA2_2 = pk2( 0.1201676f,  0.1201676f);
    const u64 NA3_2 = pk2(-0.9372980f, -0.9372980f);
    const u64 AMSK  = 0x7FFFFFFF7FFFFFFFULL;
    const u64 SMSK  = 0x8000000080000000ULL;

    u64 dk2 = 0ULL, lp2 = 0ULL;

    #pragma unroll 8
    for (int k = 0; k < CHUNK / 2; ++k) {
        float4 a = shA[k];
        float2 L = shL[k];
        u64 Rh2 = pk2(a.x, a.y);
        u64 d2  = pk2(a.z, a.w);
        u64 L2  = pk2(L.x, L.y);

        u64 dr2 = add2_(Rh2, nRhj2);               // (R_i - R_j)/h, 2 lanes
        u64 e2  = fma2_(mul2_(dr2, C1_2), dr2, C2_2);
        float elo, ehi; upk2(e2, elo, ehi);
        u64 phi2 = pk2(ex2f_(elo), ex2f_(ehi));    // normal pdf, both lanes
        dk2 = fma2_(d2, phi2, dk2);

        u64 den2 = fma2_(dr2 & AMSK, PP2, ONE2);   // 1 + p|dr|
        float dlo, dhi; upk2(den2, dlo, dhi);
        float rr = rcpf_(dlo * dhi);               // one rcp, both lanes
        u64 t2 = pk2(rr * dhi, rr * dlo);          // {1/dlo, 1/dhi}

        u64 p2 = fma2_(t2, NA3_2, NA2_2);          // -poly3(t), Horner
        p2 = fma2_(t2, p2, NA1_2);
        p2 = mul2_(t2, p2);
        u64 u2 = fma2_(phi2, p2, HALF2);           // 0.5 - q >= 0
        u64 v2 = u2 | (dr2 & SMSK);                // ndtr(dr) - 0.5
        lp2 = fma2_(L2, v2, lp2);
    }

    float dka, dkb, lpa, lpb;
    upk2(dk2, dka, dkb);
    upk2(lp2, lpa, lpb);
    if (c < M) {
        g_partDk[c * SPLITS + s] = dka + dkb;
        g_partLP[c * SPLITS + s] = lpa + lpb;
    }
}

// Epilogue: block-redundant Lsum (fixed order over g_sval), S1+S2 per j,
// contiguous LDG.128 partial gather, last block combines + resets counters.
__global__ void __launch_bounds__(256) reduce_kernel(const float* __restrict__ mz,
                                                     const float* __restrict__ y,
                                                     const float* __restrict__ delta,
                                                     float h, float* __restrict__ out) {
    __shared__ double red[256];
    __shared__ int    lastFlag;
    const int t   = threadIdx.x;
    const int gid = blockIdx.x * 256 + t;
    const int M   = g_M;

    // block-redundant Lsum from the deterministic permutation g_sval
    double ls = 0.0;
    for (int m = t; m < N; m += 256) ls += (double)fabsf(g_sval[m]);
    red[t] = ls;
    __syncthreads();
    for (int s = 128; s > 0; s >>= 1) {
        if (t < s) red[t] += red[t + s];
        __syncthreads();
    }
    const float Lsum = (float)red[0];
    __syncthreads();

    const float inv_nh = 1.0f / ((float)N * h);
    const float invn   = 1.0f / (float)N;

    double acc;
    {   // S1 + S2: d_j * (g2_j - R_j)
        float g1 = mz[2 * gid], g2 = mz[2 * gid + 1];
        float R  = g1 + logf(y[gid]);
        float d  = delta[gid] > 0.5f ? 1.0f : 0.0f;
        acc = (double)(d * (g2 - R));
    }
    // S3 + S4 over compacted columns
    if (gid < M) {
        const float4* pDk = (const float4*)&g_partDk[gid * SPLITS];
        const float4* pLP = (const float4*)&g_partLP[gid * SPLITS];
        float dk = 0.0f, lp = 0.0f;
        #pragma unroll
        for (int q = 0; q < SPLITS / 4; ++q) {
            float4 a = pDk[q], b = pLP[q];
            dk += (a.x + a.y) + (a.z + a.w);
            lp += (b.x + b.y) + (b.z + b.w);
        }
        float Dk = dk * inv_nh;
        float LP = (lp + 0.5f * Lsum) * invn;
        acc += (double)(logf(Dk + 1e-15f) - logf(LP + 1e-15f));
    }
    red[t] = acc;
    __syncthreads();
    for (int s = 128; s > 0; s >>= 1) {
        if (t < s) red[t] += red[t + s];
        __syncthreads();
    }
    if (t == 0) g_bsum[blockIdx.x] = red[0];

    __threadfence();
    if (t == 0) {
        int prev = atomicAdd(&g_ctr, 1);
        lastFlag = (prev == RB - 1);
    }
    __syncthreads();
    if (!lastFlag) return;

    if (t < 32) {
        double v = g_bsum[t];
        #pragma unroll
        for (int s = 16; s > 0; s >>= 1)
            v += __shfl_down_sync(0xFFFFFFFFu, v, s);
        if (t == 0) {
            out[0] = (float)(-v / (double)N);
            g_c1 = 0; g_ctr = 0;   // reset for next replay
        }
    }
}

extern "C" void kernel_launch(void* const* d_in, const int* in_sizes, int n_in,
                              void* d_out, int out_size) {
    const float* mz    = (const float*)d_in[0];
    const float* y     = (const float*)d_in[1];
    const float* delta = (const float*)d_in[2];
    float* out = (float*)d_out;

    const double hd = 1.3 * pow((double)N, -0.2);

    prep_kernel<<<PB, PT>>>(mz, y, delta, (float)(1.0 / hd));
    dim3 grid(GX, SPLITS);
    pair_kernel<<<grid, JT>>>();
    reduce_kernel<<<RB, 256>>>(mz, y, delta, (float)hd, out);
}

// round 17
// speedup vs baseline: 1.0351x; 1.0351x over previous
#include <cuda_runtime.h>
#include <math.h>

// DehLoss: O(n^2) pairwise Gaussian-kernel loss, n = 8192.
// R_i = g1_i + log(y_i), h = 1.3*n^-0.2, dr_ij = (R_i - R_j)/h
// Dk_j = sum_i d_i*phi(dr_ij);  LP_j = sum_i L_i*ndtr(dr_ij), L_i = exp(g2_i-g1_i)
// out = -(S1+S2+S3+S4)
//
// R17 (vs R15, one change): prep's fp64 S12/Lsum partials moved AFTER the
// grid spin (phase B, post-scatter) as warp-shfl reductions -> shorter
// pre-spin critical path for every block. Reduce identical to R15 (reads
// g_s12p/g_lsp). Pair kernel byte-identical (SPLITS=64). 3 launches.

#define N      8192
#define SPLITS 64
#define CHUNK  (N / SPLITS)   // 128 columns per split
#define JT     128
#define GX     (N / JT)       // 64 j-blocks
#define RB     32             // reduce blocks
#define PB     32             // prep blocks
#define PT     256
#define NB     64             // buckets
#define NW     (PT / 32)      // warps per prep block
#define BAND   6.0f
#define BLO    (-32.0f)       // fixed bucket range (Rh provably in +-24)

typedef unsigned long long u64;

__device__ float  g_skey[N];      // bucket-ordered Rh
__device__ float  g_sval[N];      // bucket-ordered +-L (sign = delta flag)
__device__ float  g_rowRh[N];     // bucket-ordered Rh of flagged rows
__device__ int    g_M;            // number of flagged rows
__device__ int    g_c1;           // prep spin counter (reset by reduce)
__device__ int    g_ctr;          // reduce last-block counter
__device__ double g_s12p[PB], g_lsp[PB];
__device__ int    g_hist[NB * PB], g_histF[NB * PB];   // [bucket*PB + block]
__device__ float  g_partDk[N * SPLITS];   // [c*SPLITS + s]
__device__ float  g_partLP[N * SPLITS];
__device__ double g_bsum[RB];

__device__ __forceinline__ float ex2f_(float x) {
    float r; asm("ex2.approx.ftz.f32 %0, %1;" : "=f"(r) : "f"(x)); return r;
}
__device__ __forceinline__ float rcpf_(float x) {
    float r; asm("rcp.approx.ftz.f32 %0, %1;" : "=f"(r) : "f"(x)); return r;
}
__device__ __forceinline__ u64 pk2(float lo, float hi) {
    u64 r; asm("mov.b64 %0, {%1, %2};" : "=l"(r) : "f"(lo), "f"(hi)); return r;
}
__device__ __forceinline__ void upk2(u64 v, float& lo, float& hi) {
    asm("mov.b64 {%0, %1}, %2;" : "=f"(lo), "=f"(hi) : "l"(v));
}
__device__ __forceinline__ u64 fma2_(u64 a, u64 b, u64 c) {
    u64 d; asm("fma.rn.f32x2 %0, %1, %2, %3;" : "=l"(d) : "l"(a), "l"(b), "l"(c)); return d;
}
__device__ __forceinline__ u64 mul2_(u64 a, u64 b) {
    u64 d; asm("mul.rn.f32x2 %0, %1, %2;" : "=l"(d) : "l"(a), "l"(b)); return d;
}
__device__ __forceinline__ u64 add2_(u64 a, u64 b) {
    u64 d; asm("add.rn.f32x2 %0, %1, %2;" : "=l"(d) : "l"(a), "l"(b)); return d;
}

// Resident-grid spin barrier: all PB blocks co-resident (32 << 148 SMs).
__device__ __forceinline__ void grid_spin(int* ctr, int tid) {
    __threadfence();
    __syncthreads();
    if (tid == 0) {
        atomicAdd(ctr, 1);
        volatile int* p = ctr;
        while (*p < PB) { }
    }
    __syncthreads();
    __threadfence();
}

__global__ void __launch_bounds__(PT) prep_kernel(const float* __restrict__ mz,
                                                  const float* __restrict__ y,
                                                  const float* __restrict__ delta,
                                                  float inv_h) {
    __shared__ double dws[2][NW];
    __shared__ int    sH[NB], sHF[NB];
    __shared__ int    sPb[NB], sPbF[NB];
    __shared__ int    sWs[2], sWsF[2];
    __shared__ int    H[NB * PB];     // 8 KB, [bucket*PB + block]
    __shared__ int    HF[NB * PB];    // 8 KB
    __shared__ int    W[NW * NB], WF[NW * NB];
    const int b = blockIdx.x, t = threadIdx.x;
    const int lane = t & 31, w = t >> 5;
    const int j = b * PT + t;

    // ---- phase A (pre-spin critical path, minimal): values + histogram ----
    float2 g = ((const float2*)mz)[j];
    float R    = g.x + logf(y[j]);
    float Rh   = R * inv_h;
    float L    = expf(g.y - g.x);
    int   flag = delta[j] > 0.5f;
    float val  = flag ? -L : L;
    float s12c = flag ? (g.y - R) : 0.0f;          // kept for post-spin reduce
    const int bk = min(max((int)(Rh - BLO), 0), NB - 1);   // fixed bounds, scale 1

    if (t < NB) { sH[t] = 0; sHF[t] = 0; }
    __syncthreads();
    atomicAdd(&sH[bk], 1);
    if (flag) atomicAdd(&sHF[bk], 1);
    __syncthreads();
    if (t < NB) { g_hist[t * PB + b] = sH[t]; g_histF[t * PB + b] = sHF[t]; }

    grid_spin(&g_c1, t);

    // ---- phase B: global ranks + scatter ----
    for (int k = t; k < NB * PB; k += PT) { H[k] = g_hist[k]; HF[k] = g_histF[k]; }
    for (int k = t; k < NW * NB; k += PT) { W[k] = 0; WF[k] = 0; }
    __syncthreads();

    // bucket totals + 2-warp inclusive shfl scan (threads 0..63)
    int tot = 0, totF = 0, incl = 0, inclF = 0;
    if (t < NB) {
        #pragma unroll
        for (int q = 0; q < PB; ++q) { tot += H[t * PB + q]; totF += HF[t * PB + q]; }
        incl = tot; inclF = totF;
        #pragma unroll
        for (int off = 1; off < 32; off <<= 1) {
            int n  = __shfl_up_sync(0xFFFFFFFFu, incl,  off);
            int nF = __shfl_up_sync(0xFFFFFFFFu, inclF, off);
            if (lane >= off) { incl += n; inclF += nF; }
        }
        if (lane == 31) { sWs[w] = incl; sWsF[w] = inclF; }
    }
    // stable in-warp rank (all 256 threads; independent of scan)
    unsigned mask = __match_any_sync(0xFFFFFFFFu, bk);
    unsigned ltm  = (1u << lane) - 1u;
    int rw = __popc(mask & ltm);
    unsigned flgbal = __ballot_sync(0xFFFFFFFFu, flag);
    unsigned maskF  = mask & flgbal;
    int rwF = __popc(maskF & ltm);
    if ((mask & ltm) == 0) W[w * NB + bk] = __popc(mask);
    if (flag && ((maskF & ltm) == 0)) WF[w * NB + bk] = __popc(maskF);
    __syncthreads();

    if (t < NB) {
        int add  = (t >= 32) ? sWs[0]  : 0;
        int addF = (t >= 32) ? sWsF[0] : 0;
        sPb[t]  = incl  + add  - tot;    // exclusive bucket prefix
        sPbF[t] = inclF + addF - totF;
        if (b == 0 && t == NB - 1) g_M = inclF + addF;   // total flagged
    }
    __syncthreads();

    int below = 0, belowF = 0;
    for (int q = 0; q < b; ++q) { below += H[bk * PB + q]; belowF += HF[bk * PB + q]; }
    int woff = 0, woffF = 0;
    #pragma unroll
    for (int q = 0; q < NW; ++q) {
        if (q < w) { woff += W[q * NB + bk]; woffF += WF[q * NB + bk]; }
    }
    int dest = sPb[bk] + below + woff + rw;
    g_skey[dest] = Rh;
    g_sval[dest] = val;
    if (flag) g_rowRh[sPbF[bk] + belowF + woffF + rwF] = Rh;

    // ---- post-spin fp64 partials (off the critical path): shfl reduce ----
    {
        double a = (double)s12c;
        double l = (double)L;
        #pragma unroll
        for (int o = 16; o > 0; o >>= 1) {
            a += __shfl_down_sync(0xFFFFFFFFu, a, o);
            l += __shfl_down_sync(0xFFFFFFFFu, l, o);
        }
        if (lane == 0) { dws[0][w] = a; dws[1][w] = l; }
        __syncthreads();
        if (t == 0) {
            double sa = dws[0][0], sl = dws[1][0];
            #pragma unroll
            for (int q = 1; q < NW; ++q) { sa += dws[0][q]; sl += dws[1][q]; }
            g_s12p[b] = sa; g_lsp[b] = sl;
        }
    }
}

__global__ void __launch_bounds__(JT) pair_kernel() {
    __shared__ float4 shA[CHUNK / 2];
    __shared__ float2 shL[CHUNK / 2];
    __shared__ float  wred[5][JT / 32];
    const int M = g_M;
    const int c0 = blockIdx.x * JT;
    if (c0 >= M) return;

    const int c  = c0 + threadIdx.x;
    const int cc = min(c, M - 1);
    const int s  = blockIdx.y;
    const float Rhj = g_rowRh[cc];

    // fill smem tile + per-thread chunk stats
    float cmin = 1e30f, cmax = -1e30f, cls = 0.0f;
    const int cbase = s * CHUNK;
    for (int k = threadIdx.x; k < CHUNK / 2; k += JT) {
        float kx = g_skey[cbase + 2 * k], ky = g_skey[cbase + 2 * k + 1];
        float vx = g_sval[cbase + 2 * k], vy = g_sval[cbase + 2 * k + 1];
        float ax = fabsf(vx), ay = fabsf(vy);
        shA[k] = make_float4(kx, ky, vx < 0.0f ? 1.0f : 0.0f, vy < 0.0f ? 1.0f : 0.0f);
        shL[k] = make_float2(ax, ay);
        cmin = fminf(cmin, fminf(kx, ky));
        cmax = fmaxf(cmax, fmaxf(kx, ky));
        cls += ax + ay;
    }
    float rmin = Rhj, rmax = Rhj;
    #pragma unroll
    for (int o = 16; o > 0; o >>= 1) {
        cmin = fminf(cmin, __shfl_down_sync(0xFFFFFFFFu, cmin, o));
        cmax = fmaxf(cmax, __shfl_down_sync(0xFFFFFFFFu, cmax, o));
        cls += __shfl_down_sync(0xFFFFFFFFu, cls, o);
        rmin = fminf(rmin, __shfl_down_sync(0xFFFFFFFFu, rmin, o));
        rmax = fmaxf(rmax, __shfl_down_sync(0xFFFFFFFFu, rmax, o));
    }
    {
        int w = threadIdx.x >> 5, lane = threadIdx.x & 31;
        if (lane == 0) {
            wred[0][w] = cmin; wred[1][w] = cmax; wred[2][w] = cls;
            wred[3][w] = rmin; wred[4][w] = rmax;
        }
    }
    __syncthreads();   // also orders the smem tile for the loop below
    cmin = wred[0][0]; cmax = wred[1][0]; cls = wred[2][0];
    rmin = wred[3][0]; rmax = wred[4][0];
    #pragma unroll
    for (int q = 1; q < JT / 32; ++q) {
        cmin = fminf(cmin, wred[0][q]); cmax = fmaxf(cmax, wred[1][q]); cls += wred[2][q];
        rmin = fminf(rmin, wred[3][q]); rmax = fmaxf(rmax, wred[4][q]);
    }

    // band skip: tile fully outside |dr| <= BAND -> analytic contribution
    if (cmin > rmax + BAND) {     // all dr >> 0: ndtr=1, phi=0
        if (c < M) { g_partDk[c * SPLITS + s] = 0.0f; g_partLP[c * SPLITS + s] =  0.5f * cls; }
        return;
    }
    if (cmax < rmin - BAND) {     // all dr << 0: ndtr=0, phi=0
        if (c < M) { g_partDk[c * SPLITS + s] = 0.0f; g_partLP[c * SPLITS + s] = -0.5f * cls; }
        return;
    }

    // C1 = -0.5*log2(e), C2 = log2(1/sqrt(2*pi)); AS 26.2.16 coeffs negated.
    const u64 nRhj2 = pk2(-Rhj, -Rhj);
    const u64 C1_2  = pk2(-0.72134752044448170f, -0.72134752044448170f);
    const u64 C2_2  = pk2(-1.32574806473615923f, -1.32574806473615923f);
    const u64 PP2   = pk2(0.33267f, 0.33267f);
    const u64 ONE2  = pk2(1.0f, 1.0f);
    const u64 HALF2 = pk2(0.5f, 0.5f);
    const u64 NA1_2 = pk2(-0.4361836f, -0.4361836f);
    const u64 NA2_2 = pk2( 0.1201676f,  0.1201676f);
    const u64 NA3_2 = pk2(-0.9372980f, -0.9372980f);
    const u64 AMSK  = 0x7FFFFFFF7FFFFFFFULL;
    const u64 SMSK  = 0x8000000080000000ULL;

    u64 dk2 = 0ULL, lp2 = 0ULL;

    #pragma unroll 8
    for (int k = 0; k < CHUNK / 2; ++k) {
        float4 a = shA[k];
        float2 L = shL[k];
        u64 Rh2 = pk2(a.x, a.y);
        u64 d2  = pk2(a.z, a.w);
        u64 L2  = pk2(L.x, L.y);

        u64 dr2 = add2_(Rh2, nRhj2);               // (R_i - R_j)/h, 2 lanes
        u64 e2  = fma2_(mul2_(dr2, C1_2), dr2, C2_2);
        float elo, ehi; upk2(e2, elo, ehi);
        u64 phi2 = pk2(ex2f_(elo), ex2f_(ehi));    // normal pdf, both lanes
        dk2 = fma2_(d2, phi2, dk2);

        u64 den2 = fma2_(dr2 & AMSK, PP2, ONE2);   // 1 + p|dr|
        float dlo, dhi; upk2(den2, dlo, dhi);
        float rr = rcpf_(dlo * dhi);               // one rcp, both lanes
        u64 t2 = pk2(rr * dhi, rr * dlo);          // {1/dlo, 1/dhi}

        u64 p2 = fma2_(t2, NA3_2, NA2_2);          // -poly3(t), Horner
        p2 = fma2_(t2, p2, NA1_2);
        p2 = mul2_(t2, p2);
        u64 u2 = fma2_(phi2, p2, HALF2);           // 0.5 - q >= 0
        u64 v2 = u2 | (dr2 & SMSK);                // ndtr(dr) - 0.5
        lp2 = fma2_(L2, v2, lp2);
    }

    float dka, dkb, lpa, lpb;
    upk2(dk2, dka, dkb);
    upk2(lp2, lpa, lpb);
    if (c < M) {
        g_partDk[c * SPLITS + s] = dka + dkb;
        g_partLP[c * SPLITS + s] = lpa + lpb;
    }
}

// Epilogue: contiguous LDG.128 gather per column; last block combines and
// resets the spin/last-block counters for the next graph replay.
__global__ void __launch_bounds__(256) reduce_kernel(float h, float* __restrict__ out) {
    __shared__ double red[256];
    __shared__ float  sLsum;
    __shared__ int    lastFlag;
    const int t   = threadIdx.x;
    const int gid = blockIdx.x * 256 + t;
    const int M   = g_M;

    if (t == 0) {
        double ls = 0.0;
        #pragma unroll
        for (int q = 0; q < PB; ++q) ls += g_lsp[q];
        sLsum = (float)ls;
    }
    __syncthreads();
    const float Lsum   = sLsum;
    const float inv_nh = 1.0f / ((float)N * h);
    const float invn   = 1.0f / (float)N;

    double acc = 0.0;
    if (gid < M) {
        const float4* pDk = (const float4*)&g_partDk[gid * SPLITS];
        const float4* pLP = (const float4*)&g_partLP[gid * SPLITS];
        float dk = 0.0f, lp = 0.0f;
        #pragma unroll
        for (int q = 0; q < SPLITS / 4; ++q) {
            float4 a = pDk[q], b = pLP[q];
            dk += (a.x + a.y) + (a.z + a.w);
            lp += (b.x + b.y) + (b.z + b.w);
        }
        float Dk = dk * inv_nh;
        float LP = (lp + 0.5f * Lsum) * invn;
        acc = (double)(logf(Dk + 1e-15f) - logf(LP + 1e-15f));
    }
    red[t] = acc;
    __syncthreads();
    for (int s = 128; s > 0; s >>= 1) {
        if (t < s) red[t] += red[t + s];
        __syncthreads();
    }
    if (t == 0) g_bsum[blockIdx.x] = red[0];

    __threadfence();
    if (t == 0) {
        int prev = atomicAdd(&g_ctr, 1);
        lastFlag = (prev == RB - 1);
    }
    __syncthreads();
    if (!lastFlag) return;

    if (t < 32) {
        double v = g_bsum[t];
        #pragma unroll
        for (int s = 16; s > 0; s >>= 1)
            v += __shfl_down_sync(0xFFFFFFFFu, v, s);
        if (t == 0) {
            double s12 = 0.0;
            #pragma unroll
            for (int q = 0; q < PB; ++q) s12 += g_s12p[q];
            out[0] = (float)(-(v + s12) / (double)N);
            g_c1 = 0; g_ctr = 0;   // reset for next replay
        }
    }
}

extern "C" void kernel_launch(void* const* d_in, const int* in_sizes, int n_in,
                              void* d_out, int out_size) {
    const float* mz    = (const float*)d_in[0];
    const float* y     = (const float*)d_in[1];
    const float* delta = (const float*)d_in[2];
    float* out = (float*)d_out;

    const double hd = 1.3 * pow((double)N, -0.2);

    prep_kernel<<<PB, PT>>>(mz, y, delta, (float)(1.0 / hd));
    dim3 grid(GX, SPLITS);
    pair_kernel<<<grid, JT>>>();
    reduce_kernel<<<RB, 256>>>((float)hd, out);
}